// round 10
// baseline (speedup 1.0000x reference)
#include <cuda_runtime.h>
#include <mma.h>
using namespace nvcuda;

#define NN   50000
#define EE   800000
#define ETOT 850000
#define GG   256

// ---------------- scratch (device globals; no allocation allowed) ----------------
__device__ float g_xl1[NN * 128];
__device__ float g_xr1[NN * 128];
__device__ float g_out1[NN * 128];

__device__ float g_xl2[NN * 64];
__device__ float g_xr2[NN * 64];

__device__ float g_pool[GG * 64];
__device__ float g_cnt[GG];

__device__ int g_deg[NN];
__device__ int g_row[NN + 1];
__device__ int g_cursor[NN];
__device__ int g_csrc[ETOT];

__device__ __forceinline__ float lrelu(float v, float s) { return v > 0.f ? v : v * s; }

// ---------------- init ----------------
__global__ void k_init() {
    int i = blockIdx.x * blockDim.x + threadIdx.x;
    if (i < NN) g_deg[i] = 0;
    if (i < GG * 64) g_pool[i] = 0.f;
    if (i < GG) g_cnt[i] = 0.f;
}

// ---------------- CSR build ----------------
__global__ void k_deg(const int* __restrict__ ei) {
    int e = blockIdx.x * blockDim.x + threadIdx.x;
    if (e >= ETOT) return;
    int d = (e < EE) ? ei[EE + e] : (e - EE);
    atomicAdd(&g_deg[d], 1);
}

__global__ void k_scan() {
    __shared__ int ssum[1024];
    int t = threadIdx.x;
    const int CH = (NN + 1023) / 1024;
    int lo = t * CH, hi = min(lo + CH, NN);
    int s = 0;
    for (int i = lo; i < hi; i++) s += g_deg[i];
    ssum[t] = s;
    __syncthreads();
    for (int off = 1; off < 1024; off <<= 1) {
        int v = 0;
        if (t >= off) v = ssum[t - off];
        __syncthreads();
        if (t >= off) ssum[t] += v;
        __syncthreads();
    }
    int run = (t == 0) ? 0 : ssum[t - 1];
    for (int i = lo; i < hi; i++) {
        g_row[i] = run;
        g_cursor[i] = run;
        run += g_deg[i];
    }
    if (t == 0) g_row[NN] = ETOT;
}

__global__ void k_scatter(const int* __restrict__ ei) {
    int e = blockIdx.x * blockDim.x + threadIdx.x;
    if (e >= ETOT) return;
    int s, d;
    if (e < EE) { s = ei[e]; d = ei[EE + e]; }
    else        { s = d = e - EE; }
    int pos = atomicAdd(&g_cursor[d], 1);
    g_csrc[pos] = s;
}

// ---------------- smem-tiled tf32 wmma GEMM: 128 nodes x 64 outputs per block ----------------
// in:  A[NN x 128] row-major (stride 128)
// out: out[NN x outStride], cols [0,64) of this block's slice; bias added.
// smem: sa 128*136 floats (A, tf32-pre-rounded), sb 64*136 floats (B as [col][k])
#define GSM_A (128 * 136)
#define GSM_B (64 * 136)
#define GSM_BYTES ((GSM_A + GSM_B) * 4)

__device__ __forceinline__ void gemm_tile_body(
    const float* __restrict__ A, const float* __restrict__ w64,   // w64: 64 rows x 128 (row-major)
    const float* __restrict__ bias64, float* __restrict__ outb, int outStride,
    float* sa, float* sb)
{
    int tid = threadIdx.x;
    int wid = tid >> 5, lane = tid & 31;
    int node0 = blockIdx.x * 128;

    // stage A (128 x 128) with tf32 pre-round, zero-pad past NN
    for (int i = tid; i < 128 * 32; i += 256) {
        int r = i >> 5, c = (i & 31) << 2;
        int n = node0 + r;
        float4 v = (n < NN) ? *(const float4*)(A + (size_t)n * 128 + c)
                            : make_float4(0.f, 0.f, 0.f, 0.f);
        v.x = wmma::__float_to_tf32(v.x); v.y = wmma::__float_to_tf32(v.y);
        v.z = wmma::__float_to_tf32(v.z); v.w = wmma::__float_to_tf32(v.w);
        *(float4*)(sa + r * 136 + c) = v;
    }
    // stage B (64 cols x 128 k) as [col][k], tf32 pre-round
    for (int i = tid; i < 64 * 32; i += 256) {
        int c = i >> 5, k = (i & 31) << 2;
        float4 v = *(const float4*)(w64 + (size_t)c * 128 + k);
        v.x = wmma::__float_to_tf32(v.x); v.y = wmma::__float_to_tf32(v.y);
        v.z = wmma::__float_to_tf32(v.z); v.w = wmma::__float_to_tf32(v.w);
        *(float4*)(sb + c * 136 + k) = v;
    }
    __syncthreads();

    // each warp: 16 rows x 64 cols
    wmma::fragment<wmma::accumulator, 16, 16, 8, float> acc[4];
#pragma unroll
    for (int i = 0; i < 4; i++) wmma::fill_fragment(acc[i], 0.f);

#pragma unroll
    for (int k = 0; k < 128; k += 8) {
        wmma::fragment<wmma::matrix_a, 16, 16, 8, wmma::precision::tf32, wmma::row_major> af;
        wmma::load_matrix_sync(af, sa + wid * 16 * 136 + k, 136);
#pragma unroll
        for (int j = 0; j < 4; j++) {
            wmma::fragment<wmma::matrix_b, 16, 16, 8, wmma::precision::tf32, wmma::col_major> bf;
            wmma::load_matrix_sync(bf, sb + (j * 16) * 136 + k, 136);
            wmma::mma_sync(acc[j], af, bf, acc[j]);
        }
    }

    // epilogue: stage 16x64 per warp into sa (A dead), bias + store
    __syncthreads();
    float* stw = sa + wid * 1024;
#pragma unroll
    for (int j = 0; j < 4; j++)
        wmma::store_matrix_sync(stw + j * 16, acc[j], 64, wmma::mem_row_major);
    __syncwarp();
    for (int i = lane; i < 256; i += 32) {
        int r = i >> 4, c4 = (i & 15) << 2;
        int n = node0 + wid * 16 + r;
        if (n < NN) {
            float4 v = *(float4*)(stw + r * 64 + c4);
            float4 bi = *(const float4*)(bias64 + c4);
            v.x += bi.x; v.y += bi.y; v.z += bi.z; v.w += bi.w;
            *(float4*)(outb + (size_t)n * outStride + c4) = v;
        }
    }
}

// layer-1: grid (391, 4); y: 0->xl1 lo, 1->xl1 hi, 2->xr1 lo, 3->xr1 hi
__global__ void k_gemm1(const float* __restrict__ x,
                        const float* __restrict__ wl, const float* __restrict__ bl,
                        const float* __restrict__ wr, const float* __restrict__ br) {
    extern __shared__ float sm[];
    int g = blockIdx.y;
    const float* wb = (g < 2) ? wl : wr;
    const float* bb = (g < 2) ? bl : br;
    int col0 = (g & 1) * 64;
    float* outb = ((g < 2) ? g_xl1 : g_xr1) + col0;
    gemm_tile_body(x, wb + (size_t)col0 * 128, bb + col0, outb, 128,
                   sm, sm + GSM_A);
}

// layer-2: grid (391, 2); y: 0->xl2, 1->xr2
__global__ void k_gemm2(const float* __restrict__ wl, const float* __restrict__ bl,
                        const float* __restrict__ wr, const float* __restrict__ br) {
    extern __shared__ float sm[];
    int g = blockIdx.y;
    const float* wb = (g == 0) ? wl : wr;
    const float* bb = (g == 0) ? bl : br;
    float* outb = (g == 0) ? g_xl2 : g_xr2;
    gemm_tile_body(g_out1, wb, bb, outb, 64, sm, sm + GSM_A);
}

// ---------------- layer-1 fused attention: 4x-unrolled online softmax ----------------
__global__ void k_attn1(const float* __restrict__ att, const float* __restrict__ bias1) {
    int d = (blockIdx.x * blockDim.x + threadIdx.x) >> 5;
    if (d >= NN) return;
    int lane = threadIdx.x & 31;

    float4 b  = *(const float4*)(g_xr1 + (size_t)d * 128 + lane * 4);
    float4 wa = *(const float4*)(att + lane * 4);

    int rs = g_row[d], re = g_row[d + 1];
    float m = __int_as_float(0xff800000);
    float dn = 0.f;
    float4 acc = make_float4(0.f, 0.f, 0.f, 0.f);

    int pos = rs;
    for (; pos + 4 <= re; pos += 4) {
        int s0 = g_csrc[pos], s1 = g_csrc[pos + 1], s2 = g_csrc[pos + 2], s3 = g_csrc[pos + 3];
        float4 a0 = *(const float4*)(g_xl1 + (size_t)s0 * 128 + lane * 4);
        float4 a1 = *(const float4*)(g_xl1 + (size_t)s1 * 128 + lane * 4);
        float4 a2 = *(const float4*)(g_xl1 + (size_t)s2 * 128 + lane * 4);
        float4 a3 = *(const float4*)(g_xl1 + (size_t)s3 * 128 + lane * 4);

        float p0 = wa.x * lrelu(a0.x + b.x, 0.2f) + wa.y * lrelu(a0.y + b.y, 0.2f)
                 + wa.z * lrelu(a0.z + b.z, 0.2f) + wa.w * lrelu(a0.w + b.w, 0.2f);
        float p1 = wa.x * lrelu(a1.x + b.x, 0.2f) + wa.y * lrelu(a1.y + b.y, 0.2f)
                 + wa.z * lrelu(a1.z + b.z, 0.2f) + wa.w * lrelu(a1.w + b.w, 0.2f);
        float p2 = wa.x * lrelu(a2.x + b.x, 0.2f) + wa.y * lrelu(a2.y + b.y, 0.2f)
                 + wa.z * lrelu(a2.z + b.z, 0.2f) + wa.w * lrelu(a2.w + b.w, 0.2f);
        float p3 = wa.x * lrelu(a3.x + b.x, 0.2f) + wa.y * lrelu(a3.y + b.y, 0.2f)
                 + wa.z * lrelu(a3.z + b.z, 0.2f) + wa.w * lrelu(a3.w + b.w, 0.2f);

#pragma unroll
        for (int sh = 8; sh >= 1; sh >>= 1) {
            p0 += __shfl_xor_sync(0xffffffffu, p0, sh, 16);
            p1 += __shfl_xor_sync(0xffffffffu, p1, sh, 16);
            p2 += __shfl_xor_sync(0xffffffffu, p2, sh, 16);
            p3 += __shfl_xor_sync(0xffffffffu, p3, sh, 16);
        }

        float mn = fmaxf(fmaxf(m, p0), fmaxf(fmaxf(p1, p2), p3));
        float sc = __expf(m - mn);
        float w0 = __expf(p0 - mn), w1 = __expf(p1 - mn);
        float w2 = __expf(p2 - mn), w3 = __expf(p3 - mn);
        dn = dn * sc + (w0 + w1) + (w2 + w3);
        acc.x = acc.x * sc + a0.x * w0 + a1.x * w1 + a2.x * w2 + a3.x * w3;
        acc.y = acc.y * sc + a0.y * w0 + a1.y * w1 + a2.y * w2 + a3.y * w3;
        acc.z = acc.z * sc + a0.z * w0 + a1.z * w1 + a2.z * w2 + a3.z * w3;
        acc.w = acc.w * sc + a0.w * w0 + a1.w * w1 + a2.w * w2 + a3.w * w3;
        m = mn;
    }
    for (; pos < re; pos++) {
        int s = g_csrc[pos];
        float4 a = *(const float4*)(g_xl1 + (size_t)s * 128 + lane * 4);
        float p = wa.x * lrelu(a.x + b.x, 0.2f) + wa.y * lrelu(a.y + b.y, 0.2f)
                + wa.z * lrelu(a.z + b.z, 0.2f) + wa.w * lrelu(a.w + b.w, 0.2f);
#pragma unroll
        for (int sh = 8; sh >= 1; sh >>= 1)
            p += __shfl_xor_sync(0xffffffffu, p, sh, 16);
        float mn = fmaxf(m, p);
        float sc = __expf(m - mn);
        float w  = __expf(p - mn);
        dn = dn * sc + w;
        acc.x = acc.x * sc + a.x * w;
        acc.y = acc.y * sc + a.y * w;
        acc.z = acc.z * sc + a.z * w;
        acc.w = acc.w * sc + a.w * w;
        m = mn;
    }

    float inv = 1.f / dn;
    float4 bi = *(const float4*)(bias1 + lane * 4);
    float4 o;
    o.x = lrelu(acc.x * inv + bi.x, 0.01f);
    o.y = lrelu(acc.y * inv + bi.y, 0.01f);
    o.z = lrelu(acc.z * inv + bi.z, 0.01f);
    o.w = lrelu(acc.w * inv + bi.w, 0.01f);
    *(float4*)(g_out1 + (size_t)d * 128 + lane * 4) = o;
}

// ---------------- layer-2 fused attention: 4x-unrolled + mean-pool ----------------
__global__ void k_attn2(const float* __restrict__ att, const float* __restrict__ bias2,
                        const int* __restrict__ batch) {
    int d = (blockIdx.x * blockDim.x + threadIdx.x) >> 5;
    if (d >= NN) return;
    int lane = threadIdx.x & 31;

    float2 b  = *(const float2*)(g_xr2 + (size_t)d * 64 + lane * 2);
    float2 wa = *(const float2*)(att + lane * 2);

    int rs = g_row[d], re = g_row[d + 1];
    float m = __int_as_float(0xff800000);
    float dn = 0.f;
    float2 acc = make_float2(0.f, 0.f);

    int pos = rs;
    for (; pos + 4 <= re; pos += 4) {
        int s0 = g_csrc[pos], s1 = g_csrc[pos + 1], s2 = g_csrc[pos + 2], s3 = g_csrc[pos + 3];
        float2 a0 = *(const float2*)(g_xl2 + (size_t)s0 * 64 + lane * 2);
        float2 a1 = *(const float2*)(g_xl2 + (size_t)s1 * 64 + lane * 2);
        float2 a2 = *(const float2*)(g_xl2 + (size_t)s2 * 64 + lane * 2);
        float2 a3 = *(const float2*)(g_xl2 + (size_t)s3 * 64 + lane * 2);

        float p0 = wa.x * lrelu(a0.x + b.x, 0.2f) + wa.y * lrelu(a0.y + b.y, 0.2f);
        float p1 = wa.x * lrelu(a1.x + b.x, 0.2f) + wa.y * lrelu(a1.y + b.y, 0.2f);
        float p2 = wa.x * lrelu(a2.x + b.x, 0.2f) + wa.y * lrelu(a2.y + b.y, 0.2f);
        float p3 = wa.x * lrelu(a3.x + b.x, 0.2f) + wa.y * lrelu(a3.y + b.y, 0.2f);

#pragma unroll
        for (int sh = 16; sh >= 1; sh >>= 1) {
            p0 += __shfl_xor_sync(0xffffffffu, p0, sh);
            p1 += __shfl_xor_sync(0xffffffffu, p1, sh);
            p2 += __shfl_xor_sync(0xffffffffu, p2, sh);
            p3 += __shfl_xor_sync(0xffffffffu, p3, sh);
        }

        float mn = fmaxf(fmaxf(m, p0), fmaxf(fmaxf(p1, p2), p3));
        float sc = __expf(m - mn);
        float w0 = __expf(p0 - mn), w1 = __expf(p1 - mn);
        float w2 = __expf(p2 - mn), w3 = __expf(p3 - mn);
        dn = dn * sc + (w0 + w1) + (w2 + w3);
        acc.x = acc.x * sc + a0.x * w0 + a1.x * w1 + a2.x * w2 + a3.x * w3;
        acc.y = acc.y * sc + a0.y * w0 + a1.y * w1 + a2.y * w2 + a3.y * w3;
        m = mn;
    }
    for (; pos < re; pos++) {
        int s = g_csrc[pos];
        float2 a = *(const float2*)(g_xl2 + (size_t)s * 64 + lane * 2);
        float p = wa.x * lrelu(a.x + b.x, 0.2f) + wa.y * lrelu(a.y + b.y, 0.2f);
#pragma unroll
        for (int sh = 16; sh >= 1; sh >>= 1)
            p += __shfl_xor_sync(0xffffffffu, p, sh);
        float mn = fmaxf(m, p);
        float sc = __expf(m - mn);
        float w  = __expf(p - mn);
        dn = dn * sc + w;
        acc.x = acc.x * sc + a.x * w;
        acc.y = acc.y * sc + a.y * w;
        m = mn;
    }

    float inv = 1.f / dn;
    float2 bi = *(const float2*)(bias2 + lane * 2);
    float v0 = lrelu(acc.x * inv + bi.x, 0.01f);
    float v1 = lrelu(acc.y * inv + bi.y, 0.01f);

    int g = batch[d];
    atomicAdd(&g_pool[g * 64 + lane * 2 + 0], v0);
    atomicAdd(&g_pool[g * 64 + lane * 2 + 1], v1);
    if (lane == 0) atomicAdd(&g_cnt[g], 1.f);
}

// ---------------- MLP head ----------------
__global__ void k_head(const float* __restrict__ fc1_w, const float* __restrict__ fc1_b,
                       const float* __restrict__ fc2_w, const float* __restrict__ fc2_b,
                       float* __restrict__ out) {
    __shared__ float p[64], q[64];
    int g = blockIdx.x, t = threadIdx.x;
    float cnt = fmaxf(g_cnt[g], 1.f);
    if (t < 64) p[t] = g_pool[g * 64 + t] / cnt;
    __syncthreads();
    if (t < 64) {
        float acc = fc1_b[t];
#pragma unroll
        for (int k = 0; k < 64; k++) acc += p[k] * fc1_w[t * 64 + k];
        q[t] = lrelu(acc, 0.01f);
    }
    __syncthreads();
    for (int o = t; o < 768; o += blockDim.x) {
        float acc = fc2_b[o];
#pragma unroll
        for (int k = 0; k < 64; k++) acc += q[k] * fc2_w[o * 64 + k];
        out[g * 768 + o] = acc;
    }
}

// ---------------- launch ----------------
extern "C" void kernel_launch(void* const* d_in, const int* in_sizes, int n_in,
                              void* d_out, int out_size) {
    const float* x     = (const float*)d_in[0];
    const int*   ei    = (const int*)d_in[1];
    const int*   batch = (const int*)d_in[2];
    const float* w1_l = (const float*)d_in[3];
    const float* b1_l = (const float*)d_in[4];
    const float* w1_r = (const float*)d_in[5];
    const float* b1_r = (const float*)d_in[6];
    const float* att1 = (const float*)d_in[7];
    const float* bias1 = (const float*)d_in[8];
    const float* w2_l = (const float*)d_in[9];
    const float* b2_l = (const float*)d_in[10];
    const float* w2_r = (const float*)d_in[11];
    const float* b2_r = (const float*)d_in[12];
    const float* att2 = (const float*)d_in[13];
    const float* bias2 = (const float*)d_in[14];
    const float* fc1_w = (const float*)d_in[15];
    const float* fc1_b = (const float*)d_in[16];
    const float* fc2_w = (const float*)d_in[17];
    const float* fc2_b = (const float*)d_in[18];
    float* out = (float*)d_out;

    static cudaStream_t s_side = nullptr;
    static cudaEvent_t ev_fork = nullptr, ev_join = nullptr;
    static bool attr_done = false;
    if (s_side == nullptr) {
        cudaStreamCreateWithFlags(&s_side, cudaStreamNonBlocking);
        cudaEventCreateWithFlags(&ev_fork, cudaEventDisableTiming);
        cudaEventCreateWithFlags(&ev_join, cudaEventDisableTiming);
    }
    if (!attr_done) {
        cudaFuncSetAttribute(k_gemm1, cudaFuncAttributeMaxDynamicSharedMemorySize, GSM_BYTES);
        cudaFuncSetAttribute(k_gemm2, cudaFuncAttributeMaxDynamicSharedMemorySize, GSM_BYTES);
        attr_done = true;
    }

    const int nblk = (NN + 127) / 128; // 391

    // ---- fork: CSR build on side stream, gemm1 on main stream ----
    cudaEventRecord(ev_fork, 0);
    cudaStreamWaitEvent(s_side, ev_fork, 0);

    k_init<<<(NN + 255) / 256, 256, 0, s_side>>>();
    k_deg<<<(ETOT + 255) / 256, 256, 0, s_side>>>(ei);
    k_scan<<<1, 1024, 0, s_side>>>();
    k_scatter<<<(ETOT + 255) / 256, 256, 0, s_side>>>(ei);
    cudaEventRecord(ev_join, s_side);

    k_gemm1<<<dim3(nblk, 4), 256, GSM_BYTES>>>(x, w1_l, b1_l, w1_r, b1_r);

    // ---- join ----
    cudaStreamWaitEvent(0, ev_join, 0);

    k_attn1<<<(NN * 32 + 255) / 256, 256>>>(att1, bias1);

    // layer 2
    k_gemm2<<<dim3(nblk, 2), 256, GSM_BYTES>>>(w2_l, b2_l, w2_r, b2_r);
    k_attn2<<<(NN * 32 + 255) / 256, 256>>>(att2, bias2, batch);

    // head
    k_head<<<GG, 256>>>(fc1_w, fc1_b, fc2_w, fc2_b, out);
}

// round 12
// speedup vs baseline: 1.5069x; 1.5069x over previous
#include <cuda_runtime.h>
#include <mma.h>
using namespace nvcuda;

#define NN   50000
#define EE   800000
#define ETOT 850000
#define GG   256

// ---------------- scratch (device globals; zero-initialized at load,
// and every kernel_launch call restores the zero-state invariant) ----------------
__device__ float g_xl1[NN * 128];
__device__ float g_xr1[NN * 128];
__device__ float g_out1[NN * 128];

__device__ float g_xl2[NN * 64];
__device__ float g_xr2[NN * 64];

__device__ float g_pool[GG * 64];   // zeroed by k_head after use
__device__ float g_cnt[GG];         // zeroed by k_head after use

__device__ int g_deg[NN];           // zeroed by k_scan after use
__device__ int g_row[NN + 1];
__device__ int g_cursor[NN];
__device__ int g_csrc[ETOT];

__device__ __forceinline__ float lrelu(float v, float s) { return v > 0.f ? v : v * s; }

// ---------------- CSR build: histogram (g_deg arrives zeroed) ----------------
__global__ void k_deg(const int* __restrict__ ei) {
    int e = blockIdx.x * blockDim.x + threadIdx.x;
    if (e >= ETOT) return;
    int d = (e < EE) ? ei[EE + e] : (e - EE);
    atomicAdd(&g_deg[d], 1);
}

// ---------------- CSR build: scan; re-zeroes g_deg for the next call ----------------
__global__ void k_scan() {
    __shared__ int ssum[1024];
    int t = threadIdx.x;
    const int CH = (NN + 1023) / 1024;
    int lo = t * CH, hi = min(lo + CH, NN);
    int s = 0;
    for (int i = lo; i < hi; i++) s += g_deg[i];
    ssum[t] = s;
    __syncthreads();
    for (int off = 1; off < 1024; off <<= 1) {
        int v = 0;
        if (t >= off) v = ssum[t - off];
        __syncthreads();
        if (t >= off) ssum[t] += v;
        __syncthreads();
    }
    int run = (t == 0) ? 0 : ssum[t - 1];
    for (int i = lo; i < hi; i++) {
        g_row[i] = run;
        g_cursor[i] = run;
        run += g_deg[i];
        g_deg[i] = 0;                  // restore zero-state for next call
    }
    if (t == 0) g_row[NN] = ETOT;
}

// ---------------- CSR build: scatter src by dst ----------------
__global__ void k_scatter(const int* __restrict__ ei) {
    int e = blockIdx.x * blockDim.x + threadIdx.x;
    if (e >= ETOT) return;
    int s, d;
    if (e < EE) { s = ei[e]; d = ei[EE + e]; }
    else        { s = d = e - EE; }
    int pos = atomicAdd(&g_cursor[d], 1);
    g_csrc[pos] = s;
}

// ---------------- layer-1 node transforms via tf32 wmma (R8 high-occupancy form) ----------------
__global__ void k_gemm1(const float* __restrict__ x,
                        const float* __restrict__ wl, const float* __restrict__ bl,
                        const float* __restrict__ wr, const float* __restrict__ br) {
    __shared__ float sa[32 * 136];
    __shared__ float st[8 * 256];
    int tid = threadIdx.x;
    int wid = tid >> 5, lane = tid & 31;
    int node0 = blockIdx.x * 32;

    for (int i = tid; i < 1024; i += 256) {
        int f = i * 4;
        int r = f >> 7, c = f & 127;
        int n = node0 + r;
        float4 v = (n < NN) ? *(const float4*)(x + (size_t)n * 128 + c)
                            : make_float4(0.f, 0.f, 0.f, 0.f);
        v.x = wmma::__float_to_tf32(v.x); v.y = wmma::__float_to_tf32(v.y);
        v.z = wmma::__float_to_tf32(v.z); v.w = wmma::__float_to_tf32(v.w);
        *(float4*)(sa + r * 136 + c) = v;
    }
    __syncthreads();

    int wm = wid >> 2;
    int wn = wid & 3;
    const float* wbase = (wn < 2) ? wl : wr;
    int ncol0 = (wn & 1) * 64;

    wmma::fragment<wmma::accumulator, 16, 16, 8, float> acc[4];
#pragma unroll
    for (int i = 0; i < 4; i++) wmma::fill_fragment(acc[i], 0.f);

#pragma unroll
    for (int k = 0; k < 128; k += 8) {
        wmma::fragment<wmma::matrix_a, 16, 16, 8, wmma::precision::tf32, wmma::row_major> af;
        wmma::load_matrix_sync(af, sa + wm * 16 * 136 + k, 136);
#pragma unroll
        for (int fi = 0; fi < 4; fi++) {
            wmma::fragment<wmma::matrix_b, 16, 16, 8, wmma::precision::tf32, wmma::col_major> bf;
            wmma::load_matrix_sync(bf, wbase + (size_t)(ncol0 + fi * 16) * 128 + k, 128);
#pragma unroll
            for (int i = 0; i < bf.num_elements; i++) bf.x[i] = wmma::__float_to_tf32(bf.x[i]);
            wmma::mma_sync(acc[fi], af, bf, acc[fi]);
        }
    }

    float* stw = st + wid * 256;
#pragma unroll
    for (int fi = 0; fi < 4; fi++) {
        wmma::store_matrix_sync(stw, acc[fi], 16, wmma::mem_row_major);
        __syncwarp();
        int ch = wn * 64 + fi * 16;
        const float* bias = (ch < 128) ? bl : br;
        float* outb = (ch < 128) ? g_xl1 : g_xr1;
        int chl = ch & 127;
        for (int e = lane; e < 256; e += 32) {
            int r = e >> 4, c = e & 15;
            int n = node0 + wm * 16 + r;
            if (n < NN) outb[(size_t)n * 128 + chl + c] = stw[e] + bias[chl + c];
        }
        __syncwarp();
    }
}

// ---------------- layer-1 fused attention: 4x-unrolled online softmax ----------------
__global__ void k_attn1(const float* __restrict__ att, const float* __restrict__ bias1) {
    int d = (blockIdx.x * blockDim.x + threadIdx.x) >> 5;
    if (d >= NN) return;
    int lane = threadIdx.x & 31;

    float4 b  = *(const float4*)(g_xr1 + (size_t)d * 128 + lane * 4);
    float4 wa = *(const float4*)(att + lane * 4);

    int rs = g_row[d], re = g_row[d + 1];
    float m = __int_as_float(0xff800000);
    float dn = 0.f;
    float4 acc = make_float4(0.f, 0.f, 0.f, 0.f);

    int pos = rs;
    for (; pos + 4 <= re; pos += 4) {
        int s0 = g_csrc[pos], s1 = g_csrc[pos + 1], s2 = g_csrc[pos + 2], s3 = g_csrc[pos + 3];
        float4 a0 = *(const float4*)(g_xl1 + (size_t)s0 * 128 + lane * 4);
        float4 a1 = *(const float4*)(g_xl1 + (size_t)s1 * 128 + lane * 4);
        float4 a2 = *(const float4*)(g_xl1 + (size_t)s2 * 128 + lane * 4);
        float4 a3 = *(const float4*)(g_xl1 + (size_t)s3 * 128 + lane * 4);

        float p0 = wa.x * lrelu(a0.x + b.x, 0.2f) + wa.y * lrelu(a0.y + b.y, 0.2f)
                 + wa.z * lrelu(a0.z + b.z, 0.2f) + wa.w * lrelu(a0.w + b.w, 0.2f);
        float p1 = wa.x * lrelu(a1.x + b.x, 0.2f) + wa.y * lrelu(a1.y + b.y, 0.2f)
                 + wa.z * lrelu(a1.z + b.z, 0.2f) + wa.w * lrelu(a1.w + b.w, 0.2f);
        float p2 = wa.x * lrelu(a2.x + b.x, 0.2f) + wa.y * lrelu(a2.y + b.y, 0.2f)
                 + wa.z * lrelu(a2.z + b.z, 0.2f) + wa.w * lrelu(a2.w + b.w, 0.2f);
        float p3 = wa.x * lrelu(a3.x + b.x, 0.2f) + wa.y * lrelu(a3.y + b.y, 0.2f)
                 + wa.z * lrelu(a3.z + b.z, 0.2f) + wa.w * lrelu(a3.w + b.w, 0.2f);

#pragma unroll
        for (int sh = 8; sh >= 1; sh >>= 1) {
            p0 += __shfl_xor_sync(0xffffffffu, p0, sh, 16);
            p1 += __shfl_xor_sync(0xffffffffu, p1, sh, 16);
            p2 += __shfl_xor_sync(0xffffffffu, p2, sh, 16);
            p3 += __shfl_xor_sync(0xffffffffu, p3, sh, 16);
        }

        float mn = fmaxf(fmaxf(m, p0), fmaxf(fmaxf(p1, p2), p3));
        float sc = __expf(m - mn);
        float w0 = __expf(p0 - mn), w1 = __expf(p1 - mn);
        float w2 = __expf(p2 - mn), w3 = __expf(p3 - mn);
        dn = dn * sc + (w0 + w1) + (w2 + w3);
        acc.x = acc.x * sc + a0.x * w0 + a1.x * w1 + a2.x * w2 + a3.x * w3;
        acc.y = acc.y * sc + a0.y * w0 + a1.y * w1 + a2.y * w2 + a3.y * w3;
        acc.z = acc.z * sc + a0.z * w0 + a1.z * w1 + a2.z * w2 + a3.z * w3;
        acc.w = acc.w * sc + a0.w * w0 + a1.w * w1 + a2.w * w2 + a3.w * w3;
        m = mn;
    }
    for (; pos < re; pos++) {
        int s = g_csrc[pos];
        float4 a = *(const float4*)(g_xl1 + (size_t)s * 128 + lane * 4);
        float p = wa.x * lrelu(a.x + b.x, 0.2f) + wa.y * lrelu(a.y + b.y, 0.2f)
                + wa.z * lrelu(a.z + b.z, 0.2f) + wa.w * lrelu(a.w + b.w, 0.2f);
#pragma unroll
        for (int sh = 8; sh >= 1; sh >>= 1)
            p += __shfl_xor_sync(0xffffffffu, p, sh, 16);
        float mn = fmaxf(m, p);
        float sc = __expf(m - mn);
        float w  = __expf(p - mn);
        dn = dn * sc + w;
        acc.x = acc.x * sc + a.x * w;
        acc.y = acc.y * sc + a.y * w;
        acc.z = acc.z * sc + a.z * w;
        acc.w = acc.w * sc + a.w * w;
        m = mn;
    }

    float inv = 1.f / dn;
    float4 bi = *(const float4*)(bias1 + lane * 4);
    float4 o;
    o.x = lrelu(acc.x * inv + bi.x, 0.01f);
    o.y = lrelu(acc.y * inv + bi.y, 0.01f);
    o.z = lrelu(acc.z * inv + bi.z, 0.01f);
    o.w = lrelu(acc.w * inv + bi.w, 0.01f);
    *(float4*)(g_out1 + (size_t)d * 128 + lane * 4) = o;
}

// ---------------- layer-2 node transforms via tf32 wmma (R8 form) ----------------
__global__ void k_gemm2(const float* __restrict__ wl, const float* __restrict__ bl,
                        const float* __restrict__ wr, const float* __restrict__ br) {
    __shared__ float sa[32 * 136];
    __shared__ float st[8 * 256];
    int tid = threadIdx.x;
    int wid = tid >> 5, lane = tid & 31;
    int node0 = blockIdx.x * 32;

    for (int i = tid; i < 1024; i += 256) {
        int f = i * 4;
        int r = f >> 7, c = f & 127;
        int n = node0 + r;
        float4 v = (n < NN) ? *(const float4*)(g_out1 + (size_t)n * 128 + c)
                            : make_float4(0.f, 0.f, 0.f, 0.f);
        v.x = wmma::__float_to_tf32(v.x); v.y = wmma::__float_to_tf32(v.y);
        v.z = wmma::__float_to_tf32(v.z); v.w = wmma::__float_to_tf32(v.w);
        *(float4*)(sa + r * 136 + c) = v;
    }
    __syncthreads();

    int wm = wid >> 2;
    int wn = wid & 3;
    const float* wbase = (wn < 2) ? wl : wr;
    int ncol0 = (wn & 1) * 32;

    wmma::fragment<wmma::accumulator, 16, 16, 8, float> acc[2];
#pragma unroll
    for (int i = 0; i < 2; i++) wmma::fill_fragment(acc[i], 0.f);

#pragma unroll
    for (int k = 0; k < 128; k += 8) {
        wmma::fragment<wmma::matrix_a, 16, 16, 8, wmma::precision::tf32, wmma::row_major> af;
        wmma::load_matrix_sync(af, sa + wm * 16 * 136 + k, 136);
#pragma unroll
        for (int fi = 0; fi < 2; fi++) {
            wmma::fragment<wmma::matrix_b, 16, 16, 8, wmma::precision::tf32, wmma::col_major> bf;
            wmma::load_matrix_sync(bf, wbase + (size_t)(ncol0 + fi * 16) * 128 + k, 128);
#pragma unroll
            for (int i = 0; i < bf.num_elements; i++) bf.x[i] = wmma::__float_to_tf32(bf.x[i]);
            wmma::mma_sync(acc[fi], af, bf, acc[fi]);
        }
    }

    float* stw = st + wid * 256;
#pragma unroll
    for (int fi = 0; fi < 2; fi++) {
        wmma::store_matrix_sync(stw, acc[fi], 16, wmma::mem_row_major);
        __syncwarp();
        int ch = wn * 32 + fi * 16;
        const float* bias = (ch < 64) ? bl : br;
        float* outb = (ch < 64) ? g_xl2 : g_xr2;
        int chl = ch & 63;
        for (int e = lane; e < 256; e += 32) {
            int r = e >> 4, c = e & 15;
            int n = node0 + wm * 16 + r;
            if (n < NN) outb[(size_t)n * 64 + chl + c] = stw[e] + bias[chl + c];
        }
        __syncwarp();
    }
}

// ---------------- layer-2 fused attention: 4x-unrolled + mean-pool ----------------
__global__ void k_attn2(const float* __restrict__ att, const float* __restrict__ bias2,
                        const int* __restrict__ batch) {
    int d = (blockIdx.x * blockDim.x + threadIdx.x) >> 5;
    if (d >= NN) return;
    int lane = threadIdx.x & 31;

    float2 b  = *(const float2*)(g_xr2 + (size_t)d * 64 + lane * 2);
    float2 wa = *(const float2*)(att + lane * 2);

    int rs = g_row[d], re = g_row[d + 1];
    float m = __int_as_float(0xff800000);
    float dn = 0.f;
    float2 acc = make_float2(0.f, 0.f);

    int pos = rs;
    for (; pos + 4 <= re; pos += 4) {
        int s0 = g_csrc[pos], s1 = g_csrc[pos + 1], s2 = g_csrc[pos + 2], s3 = g_csrc[pos + 3];
        float2 a0 = *(const float2*)(g_xl2 + (size_t)s0 * 64 + lane * 2);
        float2 a1 = *(const float2*)(g_xl2 + (size_t)s1 * 64 + lane * 2);
        float2 a2 = *(const float2*)(g_xl2 + (size_t)s2 * 64 + lane * 2);
        float2 a3 = *(const float2*)(g_xl2 + (size_t)s3 * 64 + lane * 2);

        float p0 = wa.x * lrelu(a0.x + b.x, 0.2f) + wa.y * lrelu(a0.y + b.y, 0.2f);
        float p1 = wa.x * lrelu(a1.x + b.x, 0.2f) + wa.y * lrelu(a1.y + b.y, 0.2f);
        float p2 = wa.x * lrelu(a2.x + b.x, 0.2f) + wa.y * lrelu(a2.y + b.y, 0.2f);
        float p3 = wa.x * lrelu(a3.x + b.x, 0.2f) + wa.y * lrelu(a3.y + b.y, 0.2f);

#pragma unroll
        for (int sh = 16; sh >= 1; sh >>= 1) {
            p0 += __shfl_xor_sync(0xffffffffu, p0, sh);
            p1 += __shfl_xor_sync(0xffffffffu, p1, sh);
            p2 += __shfl_xor_sync(0xffffffffu, p2, sh);
            p3 += __shfl_xor_sync(0xffffffffu, p3, sh);
        }

        float mn = fmaxf(fmaxf(m, p0), fmaxf(fmaxf(p1, p2), p3));
        float sc = __expf(m - mn);
        float w0 = __expf(p0 - mn), w1 = __expf(p1 - mn);
        float w2 = __expf(p2 - mn), w3 = __expf(p3 - mn);
        dn = dn * sc + (w0 + w1) + (w2 + w3);
        acc.x = acc.x * sc + a0.x * w0 + a1.x * w1 + a2.x * w2 + a3.x * w3;
        acc.y = acc.y * sc + a0.y * w0 + a1.y * w1 + a2.y * w2 + a3.y * w3;
        m = mn;
    }
    for (; pos < re; pos++) {
        int s = g_csrc[pos];
        float2 a = *(const float2*)(g_xl2 + (size_t)s * 64 + lane * 2);
        float p = wa.x * lrelu(a.x + b.x, 0.2f) + wa.y * lrelu(a.y + b.y, 0.2f);
#pragma unroll
        for (int sh = 16; sh >= 1; sh >>= 1)
            p += __shfl_xor_sync(0xffffffffu, p, sh);
        float mn = fmaxf(m, p);
        float sc = __expf(m - mn);
        float w  = __expf(p - mn);
        dn = dn * sc + w;
        acc.x = acc.x * sc + a.x * w;
        acc.y = acc.y * sc + a.y * w;
        m = mn;
    }

    float inv = 1.f / dn;
    float2 bi = *(const float2*)(bias2 + lane * 2);
    float v0 = lrelu(acc.x * inv + bi.x, 0.01f);
    float v1 = lrelu(acc.y * inv + bi.y, 0.01f);

    int g = batch[d];
    atomicAdd(&g_pool[g * 64 + lane * 2 + 0], v0);
    atomicAdd(&g_pool[g * 64 + lane * 2 + 1], v1);
    if (lane == 0) atomicAdd(&g_cnt[g], 1.f);
}

// ---------------- MLP head; re-zeroes g_pool/g_cnt for the next call ----------------
__global__ void k_head(const float* __restrict__ fc1_w, const float* __restrict__ fc1_b,
                       const float* __restrict__ fc2_w, const float* __restrict__ fc2_b,
                       float* __restrict__ out) {
    __shared__ float p[64], q[64];
    int g = blockIdx.x, t = threadIdx.x;
    float cnt = fmaxf(g_cnt[g], 1.f);        // all threads read before zeroing
    if (t < 64) p[t] = g_pool[g * 64 + t] / cnt;
    __syncthreads();
    if (t < 64) g_pool[g * 64 + t] = 0.f;    // restore zero-state
    if (t == 0) g_cnt[g] = 0.f;
    if (t < 64) {
        float acc = fc1_b[t];
#pragma unroll
        for (int k = 0; k < 64; k++) acc += p[k] * fc1_w[t * 64 + k];
        q[t] = lrelu(acc, 0.01f);
    }
    __syncthreads();
    for (int o = t; o < 768; o += blockDim.x) {
        float acc = fc2_b[o];
#pragma unroll
        for (int k = 0; k < 64; k++) acc += q[k] * fc2_w[o * 64 + k];
        out[g * 768 + o] = acc;
    }
}

// ---------------- launch ----------------
extern "C" void kernel_launch(void* const* d_in, const int* in_sizes, int n_in,
                              void* d_out, int out_size) {
    const float* x     = (const float*)d_in[0];
    const int*   ei    = (const int*)d_in[1];
    const int*   batch = (const int*)d_in[2];
    const float* w1_l = (const float*)d_in[3];
    const float* b1_l = (const float*)d_in[4];
    const float* w1_r = (const float*)d_in[5];
    const float* b1_r = (const float*)d_in[6];
    const float* att1 = (const float*)d_in[7];
    const float* bias1 = (const float*)d_in[8];
    const float* w2_l = (const float*)d_in[9];
    const float* b2_l = (const float*)d_in[10];
    const float* w2_r = (const float*)d_in[11];
    const float* b2_r = (const float*)d_in[12];
    const float* att2 = (const float*)d_in[13];
    const float* bias2 = (const float*)d_in[14];
    const float* fc1_w = (const float*)d_in[15];
    const float* fc1_b = (const float*)d_in[16];
    const float* fc2_w = (const float*)d_in[17];
    const float* fc2_b = (const float*)d_in[18];
    float* out = (float*)d_out;

    static cudaStream_t s_side = nullptr;
    static cudaEvent_t ev_fork = nullptr, ev_join = nullptr;
    if (s_side == nullptr) {
        cudaStreamCreateWithFlags(&s_side, cudaStreamNonBlocking);
        cudaEventCreateWithFlags(&ev_fork, cudaEventDisableTiming);
        cudaEventCreateWithFlags(&ev_join, cudaEventDisableTiming);
    }

    // ---- fork: CSR build on side stream, gemm1 on main stream ----
    cudaEventRecord(ev_fork, 0);
    cudaStreamWaitEvent(s_side, ev_fork, 0);

    k_deg<<<(ETOT + 255) / 256, 256, 0, s_side>>>(ei);
    k_scan<<<1, 1024, 0, s_side>>>();
    k_scatter<<<(ETOT + 255) / 256, 256, 0, s_side>>>(ei);
    cudaEventRecord(ev_join, s_side);

    k_gemm1<<<(NN + 31) / 32, 256>>>(x, w1_l, b1_l, w1_r, b1_r);

    // ---- join: attention needs both CSR and gemm1 ----
    cudaStreamWaitEvent(0, ev_join, 0);

    k_attn1<<<(NN * 32 + 255) / 256, 256>>>(att1, bias1);

    // layer 2
    k_gemm2<<<(NN + 31) / 32, 256>>>(w2_l, b2_l, w2_r, b2_r);
    k_attn2<<<(NN * 32 + 255) / 256, 256>>>(att2, bias2, batch);

    // head
    k_head<<<GG, 256>>>(fc1_w, fc1_b, fc2_w, fc2_b, out);
}